// round 12
// baseline (speedup 1.0000x reference)
#include <cuda_runtime.h>
#include <cuda_fp16.h>

#define SEQ   384
#define HID   128
#define TAB   769   // 2*SEQ+1
#define BATCH 2
#define NPAIR (BATCH * SEQ * SEQ)   // 294912
#define RCH   32    // rows per build_d block
#define PRR   16    // table rows per precompute block

// Scratch (allocation-free rule): device globals.
__device__ float  g_P [4 * TAB * HID];       // [t][row][h] = pe_t[row] @ W_t^T (+bias for t==0)
__device__ __half g_Dh[64 * TAB * HID];      // [(dq*8+dk)][row][h] fp16 (12.6 MB, L2-resident)

// ---------------------------------------------------------------------------
// Kernel 1 (v3): P_t = pe_t @ W_t^T  (769 x 128 each). Bias folded into t==0.
// 128 threads = 32 h-quads x 4 row-quads; thread tile 4 rows x 4 h.
// Per f: 1 LDS.128 (W, conflict-free) + 4 broadcast LDS.32 (pe) + 16 FFMA.
// Small smem (25KB) -> multiple blocks/SM -> FFMA rt + LDS latency hidden.
// ---------------------------------------------------------------------------
__global__ void __launch_bounds__(128) k_precompute(
        const float* __restrict__ pe_ss, const float* __restrict__ pe_se,
        const float* __restrict__ pe_es, const float* __restrict__ pe_ee,
        const float* __restrict__ W,     const float* __restrict__ bias) {
    __shared__ float peS[PRR * HID];     // 8 KB
    __shared__ float Ws[32 * 132];       // 16.9 KB (pad 132: 16B-aligned rows)

    const int t    = blockIdx.y;
    const int row0 = blockIdx.x * PRR;
    const int tid  = threadIdx.x;
    const float* pe = (t == 0) ? pe_ss : (t == 1) ? pe_se : (t == 2) ? pe_es : pe_ee;

    // Stage PRR pe rows (clamped), float4, coalesced.
    const float4* pe4 = reinterpret_cast<const float4*>(pe);
    for (int i = tid; i < PRR * 32; i += 128) {
        int row = row0 + (i >> 5);
        row = row < TAB ? row : TAB - 1;
        reinterpret_cast<float4*>(peS)[i] = pe4[row * 32 + (i & 31)];
    }

    const int h0 = (tid & 31) * 4;       // 4 output channels (lane-varying)
    const int r0 = (tid >> 5) * 4;       // 4 rows (uniform within warp -> broadcast)

    float acc[4][4] = {{0.f,0.f,0.f,0.f},{0.f,0.f,0.f,0.f},
                       {0.f,0.f,0.f,0.f},{0.f,0.f,0.f,0.f}};

    for (int f0 = 0; f0 < HID; f0 += 32) {
        __syncthreads();
        // Stage Ws[f][h] = W[h][t*128 + f0 + f]; gmem reads coalesced (f fastest).
        for (int i = tid; i < 32 * 128; i += 128) {
            int f = i & 31, h = i >> 5;
            Ws[f * 132 + h] = W[h * (4 * HID) + t * HID + f0 + f];
        }
        __syncthreads();

#pragma unroll
        for (int f = 0; f < 32; ++f) {
            float4 w = *reinterpret_cast<const float4*>(&Ws[f * 132 + h0]);
#pragma unroll
            for (int r = 0; r < 4; ++r) {
                float p = peS[(r0 + r) * HID + f0 + f];   // warp broadcast
                acc[r][0] += p * w.x; acc[r][1] += p * w.y;
                acc[r][2] += p * w.z; acc[r][3] += p * w.w;
            }
        }
    }

    float4 bv = make_float4(0.f, 0.f, 0.f, 0.f);
    if (t == 0) bv = *reinterpret_cast<const float4*>(bias + h0);
#pragma unroll
    for (int r = 0; r < 4; ++r) {
        int row = row0 + r0 + r;
        if (row < TAB) {
            float4 v = make_float4(acc[r][0] + bv.x, acc[r][1] + bv.y,
                                   acc[r][2] + bv.z, acc[r][3] + bv.w);
            reinterpret_cast<float4*>(g_P)[((t * TAB + row) * 32) + (h0 >> 2)] = v;
        }
    }
}

// ---------------------------------------------------------------------------
// Kernel 2: fused D build. Block = (row-chunk, dq). Stages A_dq / C_dq windows
// in smem; each output f4 costs ~1 LDS.128 + 1 STG.64 (fp16).
//   A_dq[r] = P0[r] + P2[r+dq]
//   C_dq[j] = P1[j] + P3[j+dq]
//   D[dq*8+dk][r] = relu(A_dq[r] + C_dq[r-dk])     (clamped rows never read)
// ---------------------------------------------------------------------------
__global__ void k_build_d() {
    __shared__ float As[RCH * HID];         // 16 KB
    __shared__ float Cs[(RCH + 7) * HID];   // 19.5 KB
    const int dq  = blockIdx.y;
    const int r0  = blockIdx.x * RCH;
    const int tid = threadIdx.x;
    const float4* P4 = reinterpret_cast<const float4*>(g_P);

    for (int i = tid; i < RCH * 32; i += 256) {
        int r = i >> 5, h4 = i & 31;
        int row  = r0 + r;    if (row  > TAB - 1) row  = TAB - 1;
        int rowq = row + dq;  if (rowq > TAB - 1) rowq = TAB - 1;
        float4 a = P4[(0 * TAB + row)  * 32 + h4];
        float4 b = P4[(2 * TAB + rowq) * 32 + h4];
        reinterpret_cast<float4*>(As)[i] = make_float4(a.x+b.x, a.y+b.y, a.z+b.z, a.w+b.w);
    }
    for (int i = tid; i < (RCH + 7) * 32; i += 256) {
        int r = i >> 5, h4 = i & 31;
        int row = r0 - 7 + r;
        if (row < 0) row = 0;
        if (row > TAB - 1) row = TAB - 1;
        int rowq = row + dq;  if (rowq > TAB - 1) rowq = TAB - 1;
        float4 a = P4[(1 * TAB + row)  * 32 + h4];
        float4 b = P4[(3 * TAB + rowq) * 32 + h4];
        reinterpret_cast<float4*>(Cs)[i] = make_float4(a.x+b.x, a.y+b.y, a.z+b.z, a.w+b.w);
    }
    __syncthreads();

    uint2* D2 = reinterpret_cast<uint2*>(g_Dh);
    for (int i = tid; i < RCH * 32; i += 256) {   // 4 iters
        int r = i >> 5, h4 = i & 31;
        int row = r0 + r;
        if (row > TAB - 1) continue;
        float4 a = reinterpret_cast<const float4*>(As)[i];
#pragma unroll
        for (int dk = 0; dk < 8; ++dk) {
            float4 c = reinterpret_cast<const float4*>(Cs)[(r + 7 - dk) * 32 + h4];
            __half2 lo = __floats2half2_rn(fmaxf(a.x + c.x, 0.f), fmaxf(a.y + c.y, 0.f));
            __half2 hi = __floats2half2_rn(fmaxf(a.z + c.z, 0.f), fmaxf(a.w + c.w, 0.f));
            uint2 u;
            u.x = *reinterpret_cast<const unsigned*>(&lo);
            u.y = *reinterpret_cast<const unsigned*>(&hi);
            D2[(((dq * 8 + dk) * TAB + row) * 32) + h4] = u;
        }
    }
}

// ---------------------------------------------------------------------------
// Kernel 3: main gather. One warp handles 8 consecutive pairs (same b,q;
// 64 | 384 so whole block shares q). Vectorized pos loads, batched D reads,
// then 8 converts + streaming STG.128.
// ---------------------------------------------------------------------------
__global__ void __launch_bounds__(256) k_fuse(
        const int* __restrict__ pos_s, const int* __restrict__ pos_e,
        float* __restrict__ out) {
    const int warp  = threadIdx.x >> 5;
    const int lane  = threadIdx.x & 31;
    const int g     = blockIdx.x * 8 + warp;
    const int pair0 = g * 8;

    const int bb = (pair0 >= SEQ * SEQ) ? 1 : 0;     // BATCH == 2
    const int r  = pair0 - bb * SEQ * SEQ;
    const int q  = r / SEQ;
    const int k0 = r - q * SEQ;
    const int base = bb * SEQ;

    const int psq = __ldg(pos_s + base + q);
    const int dq8 = (__ldg(pos_e + base + q) - psq) * 8;

    const int4 s0 = *reinterpret_cast<const int4*>(pos_s + base + k0);
    const int4 s1 = *reinterpret_cast<const int4*>(pos_s + base + k0 + 4);
    const int4 e0 = *reinterpret_cast<const int4*>(pos_e + base + k0);
    const int4 e1 = *reinterpret_cast<const int4*>(pos_e + base + k0 + 4);

    int off[8];
    off[0] = ((dq8 + e0.x - s0.x) * TAB + (psq - s0.x + SEQ)) * 32;
    off[1] = ((dq8 + e0.y - s0.y) * TAB + (psq - s0.y + SEQ)) * 32;
    off[2] = ((dq8 + e0.z - s0.z) * TAB + (psq - s0.z + SEQ)) * 32;
    off[3] = ((dq8 + e0.w - s0.w) * TAB + (psq - s0.w + SEQ)) * 32;
    off[4] = ((dq8 + e1.x - s1.x) * TAB + (psq - s1.x + SEQ)) * 32;
    off[5] = ((dq8 + e1.y - s1.y) * TAB + (psq - s1.y + SEQ)) * 32;
    off[6] = ((dq8 + e1.z - s1.z) * TAB + (psq - s1.z + SEQ)) * 32;
    off[7] = ((dq8 + e1.w - s1.w) * TAB + (psq - s1.w + SEQ)) * 32;

    const uint2* D2 = reinterpret_cast<const uint2*>(g_Dh) + lane;
    uint2 u[8];
#pragma unroll
    for (int j = 0; j < 8; ++j) u[j] = __ldg(D2 + off[j]);

    float4* o = reinterpret_cast<float4*>(out + (size_t)pair0 * HID) + lane;
#pragma unroll
    for (int j = 0; j < 8; ++j) {
        __half2 lo = *reinterpret_cast<__half2*>(&u[j].x);
        __half2 hi = *reinterpret_cast<__half2*>(&u[j].y);
        float2 f0 = __half22float2(lo);
        float2 f1 = __half22float2(hi);
        __stcs(o + j * 32, make_float4(f0.x, f0.y, f1.x, f1.y));
    }
}

// ---------------------------------------------------------------------------
extern "C" void kernel_launch(void* const* d_in, const int* in_sizes, int n_in,
                              void* d_out, int out_size) {
    const int*   pos_s = (const int*)  d_in[0];
    const int*   pos_e = (const int*)  d_in[1];
    const float* pe_ss = (const float*)d_in[2];
    const float* pe_se = (const float*)d_in[3];
    const float* pe_es = (const float*)d_in[4];
    const float* pe_ee = (const float*)d_in[5];
    const float* W     = (const float*)d_in[6];
    const float* bias  = (const float*)d_in[7];
    float* out = (float*)d_out;

    dim3 g1((TAB + PRR - 1) / PRR, 4);       // 49 x 4
    k_precompute<<<g1, 128>>>(pe_ss, pe_se, pe_es, pe_ee, W, bias);

    dim3 g2((TAB + RCH - 1) / RCH, 8);       // 25 x 8
    k_build_d<<<g2, 256>>>();

    k_fuse<<<NPAIR / 8 / 8, 256>>>(pos_s, pos_e, out);
}